// round 2
// baseline (speedup 1.0000x reference)
#include <cuda_runtime.h>
#include <math.h>

#define BB 8
#define TT 16384
#define RC 32
#define CLS 256
#define ECH 256
#define NL 40
#define DILATION 1024
#define BT (BB*TT)

// -------- scratch (device globals; no allocation allowed) --------
__device__ float g_h[BB*RC*TT];      // residual stream  (16 MB)
__device__ float g_skip[BB*RC*TT];   // skip accumulator (16 MB)
__device__ float g_u[BB*RC*TT];      // pre-BN residual conv out (16 MB)
__device__ float g_y[BB*ECH*TT];     // e1 output (128 MB)
__device__ float g_stats[512];       // per-channel sum / sumsq
__device__ float g_ab[512];          // per-channel scale / shift

__device__ __forceinline__ float sigmoidf_(float x){ return 1.f/(1.f+expf(-x)); }
__device__ __forceinline__ float mishf_(float x){
    float sp = (x > 20.f) ? x : log1pf(expf(x));
    return x * tanhf(sp);
}

// ================= start conv: h = W(32x256) @ shift1(x) + b; skip = 0 =================
__global__ void __launch_bounds__(256) k_start(const float* __restrict__ x,
                                               const float* __restrict__ sw,
                                               const float* __restrict__ sb){
    __shared__ float sX[32*128];
    __shared__ float sW[32*32];
    int tid = threadIdx.x, blk = blockIdx.x;
    int b = blk >> 7;            // grid = 8 * 128
    int t0 = (blk & 127) << 7;
    if (blk == 0 && tid < 512 && tid < 512) { if (tid < 512) g_stats[tid] = 0.f; }
    int og = tid >> 6, tj = tid & 63;
    float a0[8], a1[8];
    #pragma unroll
    for (int i = 0; i < 8; i++){ a0[i]=0.f; a1[i]=0.f; }

    for (int ch = 0; ch < 8; ch++){
        int base = ch*32;
        #pragma unroll
        for (int i = 0; i < 16; i++){
            int e = tid + i*256;
            int cc = e >> 7, j = e & 127;
            int gt = t0 + j - 1;
            sX[e] = (gt >= 0) ? x[((size_t)(b*CLS + base + cc))*TT + gt] : 0.f;
        }
        #pragma unroll
        for (int i = 0; i < 4; i++){
            int e = tid + i*256;
            int k = e >> 5, o = e & 31;
            sW[e] = sw[o*CLS + base + k];   // sW[k][o]
        }
        __syncthreads();
        #pragma unroll 8
        for (int k = 0; k < 32; k++){
            float2 in = *(const float2*)(sX + k*128 + 2*tj);
            float w[8];
            *(float4*)&w[0] = *(const float4*)(sW + k*32 + 8*og);
            *(float4*)&w[4] = *(const float4*)(sW + k*32 + 8*og + 4);
            #pragma unroll
            for (int u = 0; u < 8; u++){
                a0[u] = fmaf(w[u], in.x, a0[u]);
                a1[u] = fmaf(w[u], in.y, a1[u]);
            }
        }
        __syncthreads();
    }
    int t = t0 + 2*tj;
    #pragma unroll
    for (int i = 0; i < 8; i++){
        int c = 8*og + i;
        size_t idx = ((size_t)(b*RC + c))*TT + t;
        float bias = sb[c];
        *(float2*)&g_h[idx]    = make_float2(a0[i]+bias, a1[i]+bias);
        *(float2*)&g_skip[idx] = make_float2(0.f, 0.f);
    }
}

// ================= layer kernel A: gates + skip + residual conv + BN stats =================
__global__ void __launch_bounds__(256) k_layerA(
    const float* __restrict__ gtw, const float* __restrict__ gtb,
    const float* __restrict__ gsw, const float* __restrict__ gsb,
    const float* __restrict__ rw,  const float* __restrict__ rb)
{
    extern __shared__ float smem[];
    float* sIn  = smem;            // 64 x 128 (rows 0-31: h[t], rows 32-63: h[t-1024])
    float* sW   = smem + 8192;     // 64 x 64  transposed combined gate weights: sW[k*64+u], u=2c+s
    float* sRW  = smem + 12288;    // 32 x 32  transposed residual weights: sRW[c*32+o]
    float* sRed = smem + 13312;    // 64 reduction bins

    int tid = threadIdx.x, blk = blockIdx.x;
    int b = blk >> 7;
    int t0 = (blk & 127) << 7;
    int og = tid >> 6, tj = tid & 63;
    bool valid = (t0 >= DILATION);

    #pragma unroll
    for (int i = 0; i < 32; i++){
        int e = tid + i*256;
        int r = e >> 7, j = e & 127;
        float v;
        if (r < 32) v = g_h[((size_t)(b*RC + r))*TT + t0 + j];
        else        v = valid ? g_h[((size_t)(b*RC + (r-32)))*TT + t0 - DILATION + j] : 0.f;
        sIn[e] = v;
    }
    #pragma unroll
    for (int i = 0; i < 16; i++){
        int e = tid + i*256;
        int k = e >> 6, u = e & 63;
        int c = u >> 1, s = u & 1;
        int tap = (k < 32) ? 1 : 0;
        int kk = k & 31;
        const float* wsrc = s ? gsw : gtw;
        sW[e] = wsrc[(c*32 + kk)*2 + tap];
    }
    #pragma unroll
    for (int i = 0; i < 4; i++){
        int e = tid + i*256;
        int c = e >> 5, o = e & 31;
        sRW[e] = rw[o*32 + c];
    }
    if (tid < 64) sRed[tid] = 0.f;
    __syncthreads();

    float a0[16], a1[16];
    #pragma unroll
    for (int u = 0; u < 16; u++){ a0[u]=0.f; a1[u]=0.f; }
    const float* wbase = sW + 16*og;
    #pragma unroll 8
    for (int k = 0; k < 64; k++){
        float2 in = *(const float2*)(sIn + k*128 + 2*tj);
        float w[16];
        *(float4*)&w[0]  = *(const float4*)(wbase + k*64);
        *(float4*)&w[4]  = *(const float4*)(wbase + k*64 + 4);
        *(float4*)&w[8]  = *(const float4*)(wbase + k*64 + 8);
        *(float4*)&w[12] = *(const float4*)(wbase + k*64 + 12);
        #pragma unroll
        for (int u = 0; u < 16; u++){
            a0[u] = fmaf(w[u], in.x, a0[u]);
            a1[u] = fmaf(w[u], in.y, a1[u]);
        }
    }
    __syncthreads();

    int t = t0 + 2*tj;
    #pragma unroll
    for (int i = 0; i < 8; i++){
        int c = 8*og + i;
        float tb = gtb[c], sb2 = gsb[c];
        float gv0 = tanhf(a0[2*i] + tb) * sigmoidf_(a0[2*i+1] + sb2);
        float gv1 = tanhf(a1[2*i] + tb) * sigmoidf_(a1[2*i+1] + sb2);
        size_t idx = ((size_t)(b*RC + c))*TT + t;
        float2 sk = *(float2*)&g_skip[idx];
        sk.x += gv0; sk.y += gv1;
        *(float2*)&g_skip[idx] = sk;
        sIn[c*128 + 2*tj]     = gv0;   // reuse sIn as g-tile
        sIn[c*128 + 2*tj + 1] = gv1;
    }
    __syncthreads();

    float r0[8], r1[8];
    #pragma unroll
    for (int i = 0; i < 8; i++){ r0[i]=0.f; r1[i]=0.f; }
    #pragma unroll 8
    for (int c = 0; c < 32; c++){
        float2 gg = *(const float2*)(sIn + c*128 + 2*tj);
        float w[8];
        *(float4*)&w[0] = *(const float4*)(sRW + c*32 + 8*og);
        *(float4*)&w[4] = *(const float4*)(sRW + c*32 + 8*og + 4);
        #pragma unroll
        for (int i = 0; i < 8; i++){
            r0[i] = fmaf(w[i], gg.x, r0[i]);
            r1[i] = fmaf(w[i], gg.y, r1[i]);
        }
    }
    int lane = tid & 31;
    #pragma unroll
    for (int i = 0; i < 8; i++){
        int o = 8*og + i;
        float bias = rb[o];
        float u0 = r0[i] + bias, u1 = r1[i] + bias;
        size_t idx = ((size_t)(b*RC + o))*TT + t;
        *(float2*)&g_u[idx] = make_float2(u0, u1);
        float s = u0 + u1;
        float q = u0*u0 + u1*u1;
        #pragma unroll
        for (int off = 16; off > 0; off >>= 1){
            s += __shfl_down_sync(0xffffffffu, s, off);
            q += __shfl_down_sync(0xffffffffu, q, off);
        }
        if (lane == 0){
            atomicAdd(&sRed[o],      s);
            atomicAdd(&sRed[32 + o], q);
        }
    }
    __syncthreads();
    if (tid < 32){
        atomicAdd(&g_stats[tid],       sRed[tid]);
        atomicAdd(&g_stats[256 + tid], sRed[32 + tid]);
    }
}

// ================= finalize BN stats -> scale/shift, then zero stats =================
__global__ void k_finalize(int nch, const float* __restrict__ gamma, const float* __restrict__ beta){
    int tid = threadIdx.x;  // blockDim = 512
    if (tid < nch){
        float s = g_stats[tid], q = g_stats[256 + tid];
        float m = s * (1.f/(float)BT);
        float v = q * (1.f/(float)BT) - m*m;
        float a = gamma[tid] * rsqrtf(v + 1e-5f);
        g_ab[tid]       = a;
        g_ab[256 + tid] = beta[tid] - m*a;
    }
    __syncthreads();
    g_stats[tid] = 0.f;
}

// ================= apply BN: h += a[c]*u + b[c] =================
__global__ void __launch_bounds__(256) k_apply(){
    const float4* u4 = (const float4*)g_u;
    float4* h4 = (float4*)g_h;
    const int n4 = BB*RC*TT/4;
    for (int i = blockIdx.x*blockDim.x + threadIdx.x; i < n4; i += gridDim.x*blockDim.x){
        int c = (i >> 12) & 31;               // T/4 = 4096 float4 per (b,c)
        float a = g_ab[c], bsh = g_ab[256 + c];
        float4 u = u4[i], h = h4[i];
        h.x += fmaf(a, u.x, bsh);
        h.y += fmaf(a, u.y, bsh);
        h.z += fmaf(a, u.z, bsh);
        h.w += fmaf(a, u.w, bsh);
        h4[i] = h;
    }
}

// ================= stats of skip (for bn1) =================
__global__ void __launch_bounds__(256) k_skipstats(){
    __shared__ float sred[16];
    int blk = blockIdx.x;                 // grid = 256 rows * 8 chunks = 2048
    int row = blk >> 3;
    int chunk = blk & 7;
    int c = row & 31;
    const float4* p = (const float4*)(g_skip + (size_t)row*TT + chunk*2048);
    float s = 0.f, q = 0.f;
    int tid = threadIdx.x;
    for (int i = tid; i < 512; i += 256){
        float4 v = p[i];
        s += v.x+v.y+v.z+v.w;
        q += v.x*v.x+v.y*v.y+v.z*v.z+v.w*v.w;
    }
    #pragma unroll
    for (int off = 16; off > 0; off >>= 1){
        s += __shfl_down_sync(0xffffffffu, s, off);
        q += __shfl_down_sync(0xffffffffu, q, off);
    }
    int lane = tid & 31, w = tid >> 5;
    if (lane == 0){ sred[w] = s; sred[8 + w] = q; }
    __syncthreads();
    if (tid == 0){
        float S = 0.f, Q = 0.f;
        #pragma unroll
        for (int ww = 0; ww < 8; ww++){ S += sred[ww]; Q += sred[8 + ww]; }
        atomicAdd(&g_stats[c],       S);
        atomicAdd(&g_stats[256 + c], Q);
    }
}

// ================= e1: y = W1(256x32) @ mish(bn1(skip)) + b1, accumulate bn2 stats =================
__global__ void __launch_bounds__(256) k_e1(const float* __restrict__ w1, const float* __restrict__ b1){
    __shared__ float sM[32*64];
    __shared__ float sWT[32*256];
    __shared__ float sRed[512];
    int tid = threadIdx.x, blk = blockIdx.x;
    int b = blk >> 8;               // grid = 8 * 256
    int t0 = (blk & 255) << 6;
    #pragma unroll
    for (int i = 0; i < 32; i++){
        int e = tid + i*256;
        int k = e >> 8, o = e & 255;
        sWT[e] = w1[o*32 + k];
    }
    #pragma unroll
    for (int i = 0; i < 8; i++){
        int e = tid + i*256;
        int c = e >> 6, j = e & 63;
        float v = g_skip[((size_t)(b*RC + c))*TT + t0 + j];
        sM[e] = mishf_(fmaf(g_ab[c], v, g_ab[256 + c]));
    }
    sRed[tid] = 0.f; sRed[256 + tid] = 0.f;
    __syncthreads();

    int og = tid >> 4, tp = tid & 15;
    float4 acc[16];
    #pragma unroll
    for (int u = 0; u < 16; u++) acc[u] = make_float4(0.f,0.f,0.f,0.f);
    #pragma unroll 4
    for (int k = 0; k < 32; k++){
        float4 in = *(const float4*)(sM + k*64 + 4*tp);
        float w[16];
        *(float4*)&w[0]  = *(const float4*)(sWT + k*256 + 16*og);
        *(float4*)&w[4]  = *(const float4*)(sWT + k*256 + 16*og + 4);
        *(float4*)&w[8]  = *(const float4*)(sWT + k*256 + 16*og + 8);
        *(float4*)&w[12] = *(const float4*)(sWT + k*256 + 16*og + 12);
        #pragma unroll
        for (int u = 0; u < 16; u++){
            acc[u].x = fmaf(w[u], in.x, acc[u].x);
            acc[u].y = fmaf(w[u], in.y, acc[u].y);
            acc[u].z = fmaf(w[u], in.z, acc[u].z);
            acc[u].w = fmaf(w[u], in.w, acc[u].w);
        }
    }
    int lane16 = tid & 15;
    #pragma unroll
    for (int u = 0; u < 16; u++){
        int o = 16*og + u;
        float bias = b1[o];
        float4 v = acc[u];
        v.x += bias; v.y += bias; v.z += bias; v.w += bias;
        *(float4*)&g_y[((size_t)(b*ECH + o))*TT + t0 + 4*tp] = v;
        float s = v.x+v.y+v.z+v.w;
        float q = v.x*v.x+v.y*v.y+v.z*v.z+v.w*v.w;
        #pragma unroll
        for (int off = 8; off > 0; off >>= 1){
            s += __shfl_xor_sync(0xffffffffu, s, off);
            q += __shfl_xor_sync(0xffffffffu, q, off);
        }
        if (lane16 == 0){
            atomicAdd(&sRed[o],       s);
            atomicAdd(&sRed[256 + o], q);
        }
    }
    __syncthreads();
    atomicAdd(&g_stats[tid],       sRed[tid]);
    atomicAdd(&g_stats[256 + tid], sRed[256 + tid]);
}

// ================= e2: out = W2(256x256) @ mish(bn2(y)) + b2 =================
__global__ void __launch_bounds__(256) k_e2(const float* __restrict__ w2, const float* __restrict__ b2,
                                            float* __restrict__ out){
    extern __shared__ float smem2[];
    float* sM2 = smem2;            // 256 x 64
    float* sWT = smem2 + 16384;    // 32 x 256 weight chunk
    int tid = threadIdx.x, blk = blockIdx.x;
    int b = blk >> 8;
    int t0 = (blk & 255) << 6;
    #pragma unroll 8
    for (int i = 0; i < 64; i++){
        int e = tid + i*256;
        int c = e >> 6, j = e & 63;
        float v = g_y[((size_t)(b*ECH + c))*TT + t0 + j];
        sM2[e] = mishf_(fmaf(g_ab[c], v, g_ab[256 + c]));
    }
    int og = tid >> 4, tp = tid & 15;
    float4 acc[16];
    #pragma unroll
    for (int u = 0; u < 16; u++) acc[u] = make_float4(0.f,0.f,0.f,0.f);

    for (int kc = 0; kc < 8; kc++){
        __syncthreads();
        #pragma unroll
        for (int i = 0; i < 32; i++){
            int e = tid + i*256;
            int k = e >> 8, o = e & 255;
            sWT[e] = w2[o*256 + kc*32 + k];
        }
        __syncthreads();
        #pragma unroll 4
        for (int k = 0; k < 32; k++){
            float4 in = *(const float4*)(sM2 + (kc*32 + k)*64 + 4*tp);
            float w[16];
            *(float4*)&w[0]  = *(const float4*)(sWT + k*256 + 16*og);
            *(float4*)&w[4]  = *(const float4*)(sWT + k*256 + 16*og + 4);
            *(float4*)&w[8]  = *(const float4*)(sWT + k*256 + 16*og + 8);
            *(float4*)&w[12] = *(const float4*)(sWT + k*256 + 16*og + 12);
            #pragma unroll
            for (int u = 0; u < 16; u++){
                acc[u].x = fmaf(w[u], in.x, acc[u].x);
                acc[u].y = fmaf(w[u], in.y, acc[u].y);
                acc[u].z = fmaf(w[u], in.z, acc[u].z);
                acc[u].w = fmaf(w[u], in.w, acc[u].w);
            }
        }
    }
    #pragma unroll
    for (int u = 0; u < 16; u++){
        int o = 16*og + u;
        float bias = b2[o];
        float4 v = acc[u];
        v.x += bias; v.y += bias; v.z += bias; v.w += bias;
        *(float4*)&out[((size_t)(b*CLS + o))*TT + t0 + 4*tp] = v;
    }
}

// ================= launch =================
extern "C" void kernel_launch(void* const* d_in, const int* in_sizes, int n_in,
                              void* d_out, int out_size){
    const float* x       = (const float*)d_in[0];
    const float* start_w = (const float*)d_in[1];
    const float* start_b = (const float*)d_in[2];
    const float* gt_w    = (const float*)d_in[3];
    const float* gt_b    = (const float*)d_in[4];
    const float* gs_w    = (const float*)d_in[5];
    const float* gs_b    = (const float*)d_in[6];
    const float* res_w   = (const float*)d_in[7];
    const float* res_b   = (const float*)d_in[8];
    const float* bn_g    = (const float*)d_in[9];
    const float* bn_b    = (const float*)d_in[10];
    const float* bn1_g   = (const float*)d_in[11];
    const float* bn1_b   = (const float*)d_in[12];
    const float* e1_w    = (const float*)d_in[13];
    const float* e1_b    = (const float*)d_in[14];
    const float* bn2_g   = (const float*)d_in[15];
    const float* bn2_b   = (const float*)d_in[16];
    const float* e2_w    = (const float*)d_in[17];
    const float* e2_b    = (const float*)d_in[18];
    float* out = (float*)d_out;

    static bool attr_done = false;
    cudaFuncSetAttribute(k_layerA, cudaFuncAttributeMaxDynamicSharedMemorySize, 13376*4);
    cudaFuncSetAttribute(k_e2,     cudaFuncAttributeMaxDynamicSharedMemorySize, 24576*4);
    (void)attr_done;

    k_start<<<BB*(TT/128), 256>>>(x, start_w, start_b);

    for (int L = 0; L < NL; L++){
        k_layerA<<<BB*(TT/128), 256, 13376*4>>>(
            gt_w + (size_t)L*RC*RC*2, gt_b + L*RC,
            gs_w + (size_t)L*RC*RC*2, gs_b + L*RC,
            res_w + (size_t)L*RC*RC,  res_b + L*RC);
        k_finalize<<<1, 512>>>(RC, bn_g + L*RC, bn_b + L*RC);
        k_apply<<<2048, 256>>>();
    }

    k_skipstats<<<2048, 256>>>();
    k_finalize<<<1, 512>>>(RC, bn1_g, bn1_b);
    k_e1<<<BB*(TT/64), 256>>>(e1_w, e1_b);
    k_finalize<<<1, 512>>>(ECH, bn2_g, bn2_b);
    k_e2<<<BB*(TT/64), 256, 24576*4>>>(e2_w, e2_b, out);
}